// round 1
// baseline (speedup 1.0000x reference)
#include <cuda_runtime.h>
#include <cstdint>

// ----------------------------------------------------------------------------
// StudentQAT: binarized CNN forward.
//   conv1 (fp32) -> fake_quant8 (per-tensor absmax scale) -> sign  => ternary
//   conv2 (ternary x sign(w2)) -> sign => ternary
//   conv3 (ternary x sign(w3)) -> sign => ternary
//   avgpool2x2 -> flatten -> @ sign(w_fc).T + b_fc
//
// Strategy:
//   prep:     pack sign(w2)/sign(w3) into 48-bit (dx,c) words per (o,dy);
//             pack sign(w_fc) into dp4a-friendly bytes; zero global max.
//   conv1max: conv1 + global abs-max (atomicMax on float bits, exact).
//   fused:    per-image block: conv1 -> quant-sign -> bitmask pack ->
//             conv2/conv3 via LOP3+POPC -> pool+fc via vadd4+dp4a.
// ----------------------------------------------------------------------------

__device__ unsigned int       d_gmax_bits;
__device__ unsigned long long d_WS2[48];          // [16 o][3 dy]
__device__ unsigned long long d_WS3[96];          // [32 o][3 dy]
__device__ unsigned int       d_WFC[10 * 121 * 8]; // [(o*121+p)*8+cb] 4 sign bytes

__global__ void prep_kernel(const float* __restrict__ w2,
                            const float* __restrict__ w3,
                            const float* __restrict__ wfc) {
    int tid = threadIdx.x;
    if (tid == 0) d_gmax_bits = 0u;
    for (int i = tid; i < 48; i += blockDim.x) {
        int o = i / 3, dy = i % 3;
        unsigned long long w = 0ull;
        for (int dx = 0; dx < 3; dx++)
            for (int c = 0; c < 16; c++)
                if (w2[((o * 16 + c) * 3 + dy) * 3 + dx] > 0.0f)
                    w |= 1ull << (dx * 16 + c);
        d_WS2[i] = w;
    }
    for (int i = tid; i < 96; i += blockDim.x) {
        int o = i / 3, dy = i % 3;
        unsigned long long w = 0ull;
        for (int dx = 0; dx < 3; dx++)
            for (int c = 0; c < 16; c++)
                if (w3[((o * 16 + c) * 3 + dy) * 3 + dx] > 0.0f)
                    w |= 1ull << (dx * 16 + c);
        d_WS3[i] = w;
    }
    for (int i = tid; i < 10 * 121 * 8; i += blockDim.x) {
        int o = i / (121 * 8);
        int r = i % (121 * 8);
        int p = r / 8, cb = r % 8;
        unsigned w = 0u;
        for (int j = 0; j < 4; j++) {
            float v = wfc[o * 3872 + (4 * cb + j) * 121 + p];
            int s = (v > 0.0f) - (v < 0.0f);
            w |= ((unsigned)(s & 0xFF)) << (8 * j);
        }
        d_WFC[i] = w;
    }
}

// -------------------------- conv1 + global abs max ---------------------------
__global__ void __launch_bounds__(256)
conv1max_kernel(const float* __restrict__ x, const float* __restrict__ w1) {
    __shared__ float xs[784];
    __shared__ float w1s[144];
    __shared__ float red[8];
    int tid = threadIdx.x;
    const float* xi = x + (size_t)blockIdx.x * 784;
    for (int i = tid; i < 784; i += 256) xs[i] = xi[i];
    for (int i = tid; i < 144; i += 256) w1s[i] = w1[i];
    __syncthreads();

    float xv[27];
    int pp[3] = { tid, tid + 256, (tid + 512 < 676) ? (tid + 512) : 675 };
#pragma unroll
    for (int u = 0; u < 3; u++) {
        int p = pp[u];
        int py = p / 26, px = p % 26;
#pragma unroll
        for (int dy = 0; dy < 3; dy++)
#pragma unroll
            for (int dx = 0; dx < 3; dx++)
                xv[u * 9 + dy * 3 + dx] = xs[(py + dy) * 28 + px + dx];
    }
    float mx = 0.0f;
#pragma unroll
    for (int c = 0; c < 16; c++) {
        float w[9];
#pragma unroll
        for (int k = 0; k < 9; k++) w[k] = w1s[c * 9 + k];
#pragma unroll
        for (int u = 0; u < 3; u++) {
            float a = 0.0f;
#pragma unroll
            for (int k = 0; k < 9; k++) a = fmaf(w[k], xv[u * 9 + k], a);
            mx = fmaxf(mx, fabsf(a));
        }
    }
#pragma unroll
    for (int off = 16; off > 0; off >>= 1)
        mx = fmaxf(mx, __shfl_xor_sync(0xffffffffu, mx, off));
    if ((tid & 31) == 0) red[tid >> 5] = mx;
    __syncthreads();
    if (tid == 0) {
        float m = red[0];
#pragma unroll
        for (int i = 1; i < 8; i++) m = fmaxf(m, red[i]);
        atomicMax(&d_gmax_bits, __float_as_uint(m));
    }
}

// ------------------------------ fused forward --------------------------------
__global__ void __launch_bounds__(256)
fused_kernel(const float* __restrict__ x, const float* __restrict__ w1,
             const float* __restrict__ bfc, float* __restrict__ out) {
    __shared__ float xs[784];
    __shared__ float w1s[144];
    __shared__ unsigned short S1[676], M1[676];
    __shared__ unsigned char pc1[676];
    __shared__ unsigned short S2[576], M2[576];
    __shared__ unsigned char pc2[576];
    __shared__ unsigned long long ws2s[48];
    __shared__ unsigned long long ws3s[96];
    __shared__ unsigned int h3s[484 * 9];   // stride 9 -> conflict-free
    __shared__ int acc10[10];

    int tid = threadIdx.x;
    const float* xi = x + (size_t)blockIdx.x * 784;
    for (int i = tid; i < 784; i += 256) xs[i] = xi[i];
    for (int i = tid; i < 144; i += 256) w1s[i] = w1[i];
    for (int i = tid; i < 48; i += 256) ws2s[i] = d_WS2[i];
    for (int i = tid; i < 96; i += 256) ws3s[i] = d_WS3[i];
    if (tid < 10) acc10[tid] = 0;
    float gm = __uint_as_float(d_gmax_bits);
    float scale = gm / 127.0f + 1e-8f;
    float inv_s = 1.0f / scale;
    __syncthreads();

    // ---- stage 1: conv1 + fake-quant sign, pack per-pixel channel masks ----
    {
        float xv[27];
        int pp[3] = { tid, tid + 256, (tid + 512 < 676) ? (tid + 512) : 675 };
#pragma unroll
        for (int u = 0; u < 3; u++) {
            int p = pp[u];
            int py = p / 26, px = p % 26;
#pragma unroll
            for (int dy = 0; dy < 3; dy++)
#pragma unroll
                for (int dx = 0; dx < 3; dx++)
                    xv[u * 9 + dy * 3 + dx] = xs[(py + dy) * 28 + px + dx];
        }
        unsigned sA[3] = {0, 0, 0}, mA[3] = {0, 0, 0};
#pragma unroll
        for (int c = 0; c < 16; c++) {
            float w[9];
#pragma unroll
            for (int k = 0; k < 9; k++) w[k] = w1s[c * 9 + k];
#pragma unroll
            for (int u = 0; u < 3; u++) {
                float a = 0.0f;
#pragma unroll
                for (int k = 0; k < 9; k++) a = fmaf(w[k], xv[u * 9 + k], a);
                float q = rintf(a * inv_s);      // round-half-even = jnp.round
                if (q != 0.0f) {
                    mA[u] |= 1u << c;
                    if (q > 0.0f) sA[u] |= 1u << c;
                }
            }
        }
#pragma unroll
        for (int u = 0; u < 3; u++) {
            int p = tid + u * 256;
            if (p < 676) {
                S1[p] = (unsigned short)sA[u];
                M1[p] = (unsigned short)mA[u];
                pc1[p] = (unsigned char)__popc(mA[u]);
            }
        }
    }
    __syncthreads();

    // ---- stage 2: conv2 (ternary x +-1) via LOP3+POPC ----
    for (int p = tid; p < 576; p += 256) {
        int y = p / 24, xx = p % 24;
        unsigned long long SW[3], MW[3];
        int P3 = 0;
#pragma unroll
        for (int dy = 0; dy < 3; dy++) {
            int b = (y + dy) * 26 + xx;
            SW[dy] = (unsigned long long)S1[b] |
                     ((unsigned long long)S1[b + 1] << 16) |
                     ((unsigned long long)S1[b + 2] << 32);
            MW[dy] = (unsigned long long)M1[b] |
                     ((unsigned long long)M1[b + 1] << 16) |
                     ((unsigned long long)M1[b + 2] << 32);
            P3 += (int)pc1[b] + (int)pc1[b + 1] + (int)pc1[b + 2];
        }
        unsigned s2 = 0, m2 = 0;
#pragma unroll
        for (int o = 0; o < 16; o++) {
            int neg = 0;
#pragma unroll
            for (int dy = 0; dy < 3; dy++) {
                unsigned long long t = MW[dy] & (SW[dy] ^ ws2s[o * 3 + dy]);
                neg += __popcll(t);
            }
            int v = P3 - 2 * neg;
            if (v > 0)      { s2 |= 1u << o; m2 |= 1u << o; }
            else if (v < 0) { m2 |= 1u << o; }
        }
        S2[p] = (unsigned short)s2;
        M2[p] = (unsigned short)m2;
        pc2[p] = (unsigned char)__popc(m2);
    }
    __syncthreads();

    // ---- stage 3: conv3 -> ternary bytes packed 4-per-word for dp4a ----
    for (int p = tid; p < 484; p += 256) {
        int y = p / 22, xx = p % 22;
        unsigned long long SW[3], MW[3];
        int P3 = 0;
#pragma unroll
        for (int dy = 0; dy < 3; dy++) {
            int b = (y + dy) * 24 + xx;
            SW[dy] = (unsigned long long)S2[b] |
                     ((unsigned long long)S2[b + 1] << 16) |
                     ((unsigned long long)S2[b + 2] << 32);
            MW[dy] = (unsigned long long)M2[b] |
                     ((unsigned long long)M2[b + 1] << 16) |
                     ((unsigned long long)M2[b + 2] << 32);
            P3 += (int)pc2[b] + (int)pc2[b + 1] + (int)pc2[b + 2];
        }
        for (int ob = 0; ob < 8; ob++) {
            unsigned word = 0;
#pragma unroll
            for (int j = 0; j < 4; j++) {
                int o = ob * 4 + j;
                int neg = 0;
#pragma unroll
                for (int dy = 0; dy < 3; dy++) {
                    unsigned long long t = MW[dy] & (SW[dy] ^ ws3s[o * 3 + dy]);
                    neg += __popcll(t);
                }
                int v = P3 - 2 * neg;
                int s = (v > 0) - (v < 0);
                word |= ((unsigned)(s & 0xFF)) << (8 * j);
            }
            h3s[p * 9 + ob] = word;
        }
    }
    __syncthreads();

    // ---- stage 4: 2x2 avgpool (vadd4) + FC (dp4a with sign(w_fc)) ----
    if (tid < 121) {
        int Y = tid / 11, X = tid % 11;
        int p00 = (2 * Y) * 22 + 2 * X;
        int p01 = p00 + 1, p10 = p00 + 22, p11 = p10 + 1;
        int a[10];
#pragma unroll
        for (int o = 0; o < 10; o++) a[o] = 0;
#pragma unroll
        for (int cb = 0; cb < 8; cb++) {
            unsigned s4 = __vadd4(__vadd4(h3s[p00 * 9 + cb], h3s[p01 * 9 + cb]),
                                  __vadd4(h3s[p10 * 9 + cb], h3s[p11 * 9 + cb]));
#pragma unroll
            for (int o = 0; o < 10; o++)
                a[o] = __dp4a((int)s4, (int)d_WFC[(o * 121 + tid) * 8 + cb], a[o]);
        }
#pragma unroll
        for (int o = 0; o < 10; o++) atomicAdd(&acc10[o], a[o]);
    }
    __syncthreads();
    if (tid < 10)
        out[(size_t)blockIdx.x * 10 + tid] = 0.25f * (float)acc10[tid] + bfc[tid];
}

// ------------------------------------------------------------------ launcher
extern "C" void kernel_launch(void* const* d_in, const int* in_sizes, int n_in,
                              void* d_out, int out_size) {
    const float* x   = (const float*)d_in[0];
    const float* w1  = (const float*)d_in[1];
    const float* w2  = (const float*)d_in[2];
    const float* w3  = (const float*)d_in[3];
    const float* wfc = (const float*)d_in[4];
    const float* bfc = (const float*)d_in[5];
    float* out = (float*)d_out;

    int B = in_sizes[0] / 784;

    prep_kernel<<<1, 256>>>(w2, w3, wfc);
    conv1max_kernel<<<B, 256>>>(x, w1);
    fused_kernel<<<B, 256>>>(x, w1, bfc, out);
}

// round 2
// speedup vs baseline: 1.3572x; 1.3572x over previous
#include <cuda_runtime.h>
#include <cstdint>

// ----------------------------------------------------------------------------
// StudentQAT binarized CNN forward, round 2.
//   conv1 fp32 (f32x2-packed) -> fake_quant8 sign -> ternary bitmasks
//   conv2/conv3 ternary via 5-word LOP3+POPC with __constant__ weights
//   avgpool+fc via vadd4 + dp4a
// ----------------------------------------------------------------------------

__device__ unsigned d_gmax_bits;
__device__ unsigned d_W2p[16 * 8];
__device__ unsigned d_W3p[32 * 8];
__device__ unsigned d_WFC[10 * 121 * 8];
__constant__ unsigned c_W2[16 * 8];
__constant__ unsigned c_W3[32 * 8];

// ------------------------------ f32x2 helpers --------------------------------
__device__ __forceinline__ unsigned long long pack2(float lo, float hi) {
    unsigned long long r;
    asm("mov.b64 %0, {%1, %2};" : "=l"(r) : "f"(lo), "f"(hi));
    return r;
}
__device__ __forceinline__ void unpack2(unsigned long long v, float& lo, float& hi) {
    asm("mov.b64 {%0, %1}, %2;" : "=f"(lo), "=f"(hi) : "l"(v));
}
__device__ __forceinline__ unsigned long long fma2(unsigned long long a,
                                                   unsigned long long b,
                                                   unsigned long long c) {
    unsigned long long d;
    asm("fma.rn.f32x2 %0, %1, %2, %3;" : "=l"(d) : "l"(a), "l"(b), "l"(c));
    return d;
}

// ---------------------------------- prep -------------------------------------
__global__ void prep_kernel(const float* __restrict__ w2,
                            const float* __restrict__ w3,
                            const float* __restrict__ wfc) {
    int gid = blockIdx.x * blockDim.x + threadIdx.x;
    int nt = gridDim.x * blockDim.x;
    if (gid == 0) d_gmax_bits = 0u;
    for (int o = gid; o < 16; o += nt) {
        unsigned w[5] = {0, 0, 0, 0, 0};
        for (int dy = 0; dy < 3; dy++)
            for (int dx = 0; dx < 3; dx++)
                for (int c = 0; c < 16; c++)
                    if (w2[((o * 16 + c) * 3 + dy) * 3 + dx] > 0.0f) {
                        int t = dy * 48 + dx * 16 + c;
                        w[t >> 5] |= 1u << (t & 31);
                    }
        for (int i = 0; i < 8; i++) d_W2p[o * 8 + i] = (i < 5) ? w[i] : 0u;
    }
    for (int o = gid; o < 32; o += nt) {
        unsigned w[5] = {0, 0, 0, 0, 0};
        for (int dy = 0; dy < 3; dy++)
            for (int dx = 0; dx < 3; dx++)
                for (int c = 0; c < 16; c++)
                    if (w3[((o * 16 + c) * 3 + dy) * 3 + dx] > 0.0f) {
                        int t = dy * 48 + dx * 16 + c;
                        w[t >> 5] |= 1u << (t & 31);
                    }
        for (int i = 0; i < 8; i++) d_W3p[o * 8 + i] = (i < 5) ? w[i] : 0u;
    }
    for (int i = gid; i < 10 * 121 * 8; i += nt) {
        int o = i / (121 * 8);
        int r = i % (121 * 8);
        int p = r / 8, cb = r % 8;
        unsigned w = 0u;
        for (int j = 0; j < 4; j++) {
            float v = wfc[o * 3872 + (4 * cb + j) * 121 + p];
            int s = (v > 0.0f) - (v < 0.0f);
            w |= ((unsigned)(s & 0xFF)) << (8 * j);
        }
        d_WFC[i] = w;
    }
}

// -------------------------- conv1 + global abs max ---------------------------
__global__ void __launch_bounds__(256)
conv1max_kernel(const float* __restrict__ x, const float* __restrict__ w1) {
    __shared__ float xs[784];
    __shared__ float2 wp[72];   // wp[cc*9+k] = (w1[2cc][k], w1[2cc+1][k])
    __shared__ float red[8];
    int tid = threadIdx.x;
    const float* xi = x + (size_t)blockIdx.x * 784;
    for (int i = tid; i < 784; i += 256) xs[i] = xi[i];
    for (int i = tid; i < 72; i += 256) {
        int cc = i / 9, k = i % 9;
        wp[i] = make_float2(w1[(2 * cc) * 9 + k], w1[(2 * cc + 1) * 9 + k]);
    }
    __syncthreads();

    int p0 = tid, p1 = tid + 256, p2 = (tid + 512 < 676) ? (tid + 512) : 675;
    int pys[3] = {p0 / 26, p1 / 26, p2 / 26};
    int pxs[3] = {p0 % 26, p1 % 26, p2 % 26};
    unsigned long long xd[27];
#pragma unroll
    for (int u = 0; u < 3; u++)
#pragma unroll
        for (int dy = 0; dy < 3; dy++)
#pragma unroll
            for (int dx = 0; dx < 3; dx++) {
                float v = xs[(pys[u] + dy) * 28 + pxs[u] + dx];
                xd[u * 9 + dy * 3 + dx] = pack2(v, v);
            }

    float mx = 0.0f;
#pragma unroll
    for (int cc = 0; cc < 8; cc++) {
        unsigned long long acc[3] = {0ull, 0ull, 0ull};
#pragma unroll
        for (int k = 0; k < 9; k++) {
            unsigned long long wk =
                *reinterpret_cast<const unsigned long long*>(&wp[cc * 9 + k]);
#pragma unroll
            for (int u = 0; u < 3; u++) acc[u] = fma2(xd[u * 9 + k], wk, acc[u]);
        }
#pragma unroll
        for (int u = 0; u < 3; u++) {
            float alo, ahi;
            unpack2(acc[u], alo, ahi);
            mx = fmaxf(mx, fmaxf(fabsf(alo), fabsf(ahi)));
        }
    }
#pragma unroll
    for (int off = 16; off > 0; off >>= 1)
        mx = fmaxf(mx, __shfl_xor_sync(0xffffffffu, mx, off));
    if ((tid & 31) == 0) red[tid >> 5] = mx;
    __syncthreads();
    if (tid == 0) {
        float m = red[0];
#pragma unroll
        for (int i = 1; i < 8; i++) m = fmaxf(m, red[i]);
        atomicMax(&d_gmax_bits, __float_as_uint(m));
    }
}

// ------------------------------ fused forward --------------------------------
__global__ void __launch_bounds__(256)
fused_kernel(const float* __restrict__ x, const float* __restrict__ w1,
             const float* __restrict__ bfc, float* __restrict__ out) {
    __shared__ float xs[784];
    __shared__ float2 wp[72];
    __shared__ unsigned SM1[676];      // S | M<<16
    __shared__ unsigned SM2[576];      // S | M<<16
    __shared__ unsigned h3s[484 * 9];  // stride 9 -> conflict-free
    __shared__ int acc10[10];

    int tid = threadIdx.x;
    const float* xi = x + (size_t)blockIdx.x * 784;
    for (int i = tid; i < 784; i += 256) xs[i] = xi[i];
    for (int i = tid; i < 72; i += 256) {
        int cc = i / 9, k = i % 9;
        wp[i] = make_float2(w1[(2 * cc) * 9 + k], w1[(2 * cc + 1) * 9 + k]);
    }
    if (tid < 10) acc10[tid] = 0;
    float gm = __uint_as_float(d_gmax_bits);
    float scale = gm / 127.0f + 1e-8f;
    float inv_s = 1.0f / scale;
    __syncthreads();

    // ---- stage 1: conv1 (f32x2, channel-paired) + quant-sign pack ----
    {
        int p0 = tid, p1 = tid + 256, p2 = (tid + 512 < 676) ? (tid + 512) : 675;
        int pys[3] = {p0 / 26, p1 / 26, p2 / 26};
        int pxs[3] = {p0 % 26, p1 % 26, p2 % 26};
        unsigned long long xd[27];
#pragma unroll
        for (int u = 0; u < 3; u++)
#pragma unroll
            for (int dy = 0; dy < 3; dy++)
#pragma unroll
                for (int dx = 0; dx < 3; dx++) {
                    float v = xs[(pys[u] + dy) * 28 + pxs[u] + dx];
                    xd[u * 9 + dy * 3 + dx] = pack2(v, v);
                }
        unsigned sA[3] = {0, 0, 0}, mA[3] = {0, 0, 0};
#pragma unroll
        for (int cc = 0; cc < 8; cc++) {
            unsigned long long acc[3] = {0ull, 0ull, 0ull};
#pragma unroll
            for (int k = 0; k < 9; k++) {
                unsigned long long wk =
                    *reinterpret_cast<const unsigned long long*>(&wp[cc * 9 + k]);
#pragma unroll
                for (int u = 0; u < 3; u++) acc[u] = fma2(xd[u * 9 + k], wk, acc[u]);
            }
#pragma unroll
            for (int u = 0; u < 3; u++) {
                float alo, ahi;
                unpack2(acc[u], alo, ahi);
                float qlo = rintf(alo * inv_s);
                float qhi = rintf(ahi * inv_s);
                int c0 = 2 * cc, c1 = 2 * cc + 1;
                if (qlo != 0.0f) { mA[u] |= 1u << c0; if (qlo > 0.0f) sA[u] |= 1u << c0; }
                if (qhi != 0.0f) { mA[u] |= 1u << c1; if (qhi > 0.0f) sA[u] |= 1u << c1; }
            }
        }
        SM1[p0] = sA[0] | (mA[0] << 16);
        SM1[p1] = sA[1] | (mA[1] << 16);
        SM1[p2] = sA[2] | (mA[2] << 16);   // clamped threads rewrite same value
    }
    __syncthreads();

    // ---- stage 2: conv2, 5-word ternary popcount ----
    for (int p = tid; p < 576; p += 256) {
        int y = p / 24, xx = p % 24;
        const unsigned* r0 = &SM1[y * 26 + xx];
        unsigned a0 = r0[0], b0 = r0[1], c0 = r0[2];
        unsigned a1 = r0[26], b1 = r0[27], c1 = r0[28];
        unsigned a2 = r0[52], b2 = r0[53], c2 = r0[54];
        unsigned S0 = __byte_perm(a0, b0, 0x5410), M0 = __byte_perm(a0, b0, 0x7632);
        unsigned S1 = __byte_perm(c0, a1, 0x5410), M1 = __byte_perm(c0, a1, 0x7632);
        unsigned S2 = __byte_perm(b1, c1, 0x5410), M2 = __byte_perm(b1, c1, 0x7632);
        unsigned S3 = __byte_perm(a2, b2, 0x5410), M3 = __byte_perm(a2, b2, 0x7632);
        unsigned S4 = c2 & 0xFFFFu,               M4 = c2 >> 16;
        int P3 = __popc(M0) + __popc(M1) + __popc(M2) + __popc(M3) + __popc(M4);
        unsigned sm = 0;
#pragma unroll
        for (int o = 0; o < 16; o++) {
            const unsigned* W = &c_W2[o * 8];
            int neg = __popc(M0 & (S0 ^ W[0])) + __popc(M1 & (S1 ^ W[1])) +
                      __popc(M2 & (S2 ^ W[2])) + __popc(M3 & (S3 ^ W[3])) +
                      __popc(M4 & (S4 ^ W[4]));
            int v = P3 - 2 * neg;
            unsigned pos = (unsigned)(v > 0);
            unsigned nz = (unsigned)(v != 0);
            sm |= (pos << o) | (nz << (16 + o));
        }
        SM2[p] = sm;
    }
    __syncthreads();

    // ---- stage 3: conv3 -> ternary sign bytes packed for dp4a ----
    for (int p = tid; p < 484; p += 256) {
        int y = p / 22, xx = p % 22;
        const unsigned* r0 = &SM2[y * 24 + xx];
        unsigned a0 = r0[0], b0 = r0[1], c0 = r0[2];
        unsigned a1 = r0[24], b1 = r0[25], c1 = r0[26];
        unsigned a2 = r0[48], b2 = r0[49], c2 = r0[50];
        unsigned S0 = __byte_perm(a0, b0, 0x5410), M0 = __byte_perm(a0, b0, 0x7632);
        unsigned S1 = __byte_perm(c0, a1, 0x5410), M1 = __byte_perm(c0, a1, 0x7632);
        unsigned S2 = __byte_perm(b1, c1, 0x5410), M2 = __byte_perm(b1, c1, 0x7632);
        unsigned S3 = __byte_perm(a2, b2, 0x5410), M3 = __byte_perm(a2, b2, 0x7632);
        unsigned S4 = c2 & 0xFFFFu,               M4 = c2 >> 16;
        int P3 = __popc(M0) + __popc(M1) + __popc(M2) + __popc(M3) + __popc(M4);
#pragma unroll
        for (int ob = 0; ob < 8; ob++) {
            unsigned word = 0;
#pragma unroll
            for (int j = 0; j < 4; j++) {
                int o = ob * 4 + j;
                const unsigned* W = &c_W3[o * 8];
                int neg = __popc(M0 & (S0 ^ W[0])) + __popc(M1 & (S1 ^ W[1])) +
                          __popc(M2 & (S2 ^ W[2])) + __popc(M3 & (S3 ^ W[3])) +
                          __popc(M4 & (S4 ^ W[4]));
                int v = P3 - 2 * neg;
                int s = (v >> 31) - ((-v) >> 31);   // sign in {-1,0,1}
                word |= ((unsigned)(s & 0xFF)) << (8 * j);
            }
            h3s[p * 9 + ob] = word;
        }
    }
    __syncthreads();

    // ---- stage 4: 2x2 avgpool (vadd4) + FC (dp4a) ----
    if (tid < 121) {
        int Y = tid / 11, X = tid % 11;
        int p00 = (2 * Y) * 22 + 2 * X;
        int p01 = p00 + 1, p10 = p00 + 22, p11 = p10 + 1;
        int a[10];
#pragma unroll
        for (int o = 0; o < 10; o++) a[o] = 0;
#pragma unroll
        for (int cb = 0; cb < 8; cb++) {
            unsigned s4 = __vadd4(__vadd4(h3s[p00 * 9 + cb], h3s[p01 * 9 + cb]),
                                  __vadd4(h3s[p10 * 9 + cb], h3s[p11 * 9 + cb]));
#pragma unroll
            for (int o = 0; o < 10; o++)
                a[o] = __dp4a((int)s4, (int)__ldg(&d_WFC[(o * 121 + tid) * 8 + cb]), a[o]);
        }
#pragma unroll
        for (int o = 0; o < 10; o++) atomicAdd(&acc10[o], a[o]);
    }
    __syncthreads();
    if (tid < 10)
        out[(size_t)blockIdx.x * 10 + tid] = 0.25f * (float)acc10[tid] + bfc[tid];
}

// ------------------------------------------------------------------ launcher
extern "C" void kernel_launch(void* const* d_in, const int* in_sizes, int n_in,
                              void* d_out, int out_size) {
    const float* x   = (const float*)d_in[0];
    const float* w1  = (const float*)d_in[1];
    const float* w2  = (const float*)d_in[2];
    const float* w3  = (const float*)d_in[3];
    const float* wfc = (const float*)d_in[4];
    const float* bfc = (const float*)d_in[5];
    float* out = (float*)d_out;

    int B = in_sizes[0] / 784;

    prep_kernel<<<32, 256>>>(w2, w3, wfc);

    void *s2 = nullptr, *s3 = nullptr, *t2 = nullptr, *t3 = nullptr;
    cudaGetSymbolAddress(&s2, d_W2p);
    cudaGetSymbolAddress(&t2, c_W2);
    cudaGetSymbolAddress(&s3, d_W3p);
    cudaGetSymbolAddress(&t3, c_W3);
    cudaMemcpyAsync(t2, s2, 16 * 8 * sizeof(unsigned), cudaMemcpyDeviceToDevice, 0);
    cudaMemcpyAsync(t3, s3, 32 * 8 * sizeof(unsigned), cudaMemcpyDeviceToDevice, 0);

    conv1max_kernel<<<B, 256>>>(x, w1);
    fused_kernel<<<B, 256>>>(x, w1, bfc, out);
}